// round 14
// baseline (speedup 1.0000x reference)
#include <cuda_runtime.h>
#include <cstdint>
#include <climits>

#define BB   4
#define N1   16384
#define N2   4096
#define CC   128
#define CIN  384
#define CH   256
#define TN   64
#define SEG  8
#define SEGN (N2 / SEG)          // 512 candidates, 128 quads per segment
#define QMASK 0xFFFFFF80u

#define SXS  72                  // X/Y row stride (floats): conflict-free frag reads
#define WT   576                 // per-warp per-buffer W tile: 16 oc x 36 floats
#define SX_FLOATS (CIN * SXS)    // 27648
#define SW_TOT    (16 * 3 * WT)  // 27648
#define SMEM_MLP_BYTES ((SX_FLOATS + SW_TOT + 64) * 4)   // 221440

// prep_kernel grid partition
#define PREP_T0   2048
#define PREP_F0   (PREP_T0 + 384)
#define PREP_END  (PREP_F0 + 64)

// ------------------- scratch -------------------
__device__ float4 g_xyz2n[BB * N2];
__device__ uint4  g_pk[BB * SEG * N1];
__device__ float4 g_w4[BB * N1];
__device__ int4   g_i4[BB * N1];
__device__ float  g_p2t[BB * N2 * CC];
__device__ float  g_W0a[CH * CIN];           // folded W0 (oc, k) row-major, tf32
__device__ float  g_W1a[CH * CH];            // folded W1 (oc, k) row-major, tf32
__device__ float  g_b0f[CH];
__device__ float  g_b1f[CH];

// ------------------- helpers -------------------
__device__ __forceinline__ float cvt_tf32(float x) {
    unsigned u;
    asm("cvt.rna.tf32.f32 %0, %1;" : "=r"(u) : "f"(x));
    return __uint_as_float(u);
}

__device__ __forceinline__ void mma8(float* d, const unsigned* a, const unsigned* b) {
    asm("mma.sync.aligned.m16n8k8.row.col.f32.tf32.tf32.f32 "
        "{%0,%1,%2,%3}, {%4,%5,%6,%7}, {%8,%9}, {%0,%1,%2,%3};\n"
        : "+f"(d[0]), "+f"(d[1]), "+f"(d[2]), "+f"(d[3])
        : "r"(a[0]), "r"(a[1]), "r"(a[2]), "r"(a[3]), "r"(b[0]), "r"(b[1]));
}

__device__ __forceinline__ void cp16(float* s, const float* g) {
    unsigned sa = (unsigned)__cvta_generic_to_shared(s);
    asm volatile("cp.async.cg.shared.global [%0], [%1], 16;\n" :: "r"(sa), "l"(g));
}
#define CP_COMMIT() asm volatile("cp.async.commit_group;\n")
#define CPW1() asm volatile("cp.async.wait_group 1;\n")
#define CPW0() asm volatile("cp.async.wait_group 0;\n")

// sorted-3 insert over signed-int keys (5 min/max)
__device__ __forceinline__ void kins3(int k, int& K0, int& K1, int& K2) {
    int t0 = min(K0, k), u0 = max(K0, k);
    int t1 = min(K1, u0), u1 = max(K1, u0);
    K2 = min(K2, u1); K0 = t0; K1 = t1;
}
__device__ __forceinline__ void ins3(float s, int j,
                                     float& a0, float& a1, float& a2,
                                     int& i0, int& i1, int& i2) {
    if (s < a2) {
        if (s < a1) {
            a2 = a1; i2 = i1;
            if (s < a0) { a1 = a0; i1 = i0; a0 = s; i0 = j; }
            else        { a1 = s;  i1 = j; }
        } else { a2 = s; i2 = j; }
    }
}

// ------------------- K1: fused prep (transpose + fold + pack) -------------------
__global__ void __launch_bounds__(256) prep_kernel(
    const float* __restrict__ p2, const float* __restrict__ xyz2,
    const float* __restrict__ w0, const float* __restrict__ b0,
    const float* __restrict__ g0, const float* __restrict__ be0,
    const float* __restrict__ m0, const float* __restrict__ v0,
    const float* __restrict__ w1, const float* __restrict__ b1,
    const float* __restrict__ g1, const float* __restrict__ be1,
    const float* __restrict__ m1, const float* __restrict__ v1) {
    __shared__ float tile[32][33];
    int blk = blockIdx.x;
    int tid = threadIdx.x;

    if (blk < PREP_T0) {
        int b = blk >> 9;
        int rem = blk & 511;
        int cb = (rem >> 7) * 32;
        int nb = (rem & 127) * 32;
        int tx = tid & 31, ty = tid >> 5;
        #pragma unroll
        for (int i = 0; i < 32; i += 8)
            tile[ty + i][tx] = p2[((size_t)b * CC + cb + ty + i) * N2 + nb + tx];
        __syncthreads();
        #pragma unroll
        for (int i = 0; i < 32; i += 8)
            g_p2t[((size_t)b * N2 + nb + ty + i) * CC + cb + tx] = tile[tx][ty + i];
    } else if (blk < PREP_F0) {
        int t = (blk - PREP_T0) * 256 + tid;
        if (t < CH * CIN) {
            int o = t / CIN;
            float s = g0[o] * rsqrtf(v0[o] + 1e-5f);
            g_W0a[t] = cvt_tf32(w0[t] * s);
        }
        if (t < CH * CH) {
            int o = t / CH;
            float s = g1[o] * rsqrtf(v1[o] + 1e-5f);
            g_W1a[t] = cvt_tf32(w1[t] * s);
        }
        if (t < CH) {
            float s0 = g0[t] * rsqrtf(v0[t] + 1e-5f);
            g_b0f[t] = (b0[t] - m0[t]) * s0 + be0[t];
            float s1 = g1[t] * rsqrtf(v1[t] + 1e-5f);
            g_b1f[t] = (b1[t] - m1[t]) * s1 + be1[t];
        }
    } else {
        int t = (blk - PREP_F0) * 256 + tid;
        if (t < BB * N2) {
            float x = xyz2[3 * t], y = xyz2[3 * t + 1], z = xyz2[3 * t + 2];
            g_xyz2n[t] = make_float4(x, y, z, x * x + y * y + z * z);
        }
    }
}

// ------------------- K2: quad-min 3-NN scan (SEG=8) -------------------
__global__ void __launch_bounds__(256) knn_part(const float* __restrict__ xyz1) {
    __shared__ float4 sP[SEGN];      // 8 KB
    int b = blockIdx.z, seg = blockIdx.y;
    int t = threadIdx.x;
    for (int i = t; i < SEGN; i += 256) sP[i] = g_xyz2n[b * N2 + seg * SEGN + i];
    __syncthreads();

    int q0 = blockIdx.x * 512 + t, q1 = q0 + 256;
    const float* p0 = xyz1 + ((size_t)b * N1 + q0) * 3;
    const float* p1 = xyz1 + ((size_t)b * N1 + q1) * 3;
    float x0 = p0[0], y0 = p0[1], z0 = p0[2];
    float x1 = p1[0], y1 = p1[1], z1 = p1[2];
    float ax0 = -2.f * x0, ay0 = -2.f * y0, az0 = -2.f * z0;
    float ax1 = -2.f * x1, ay1 = -2.f * y1, az1 = -2.f * z1;
    float nq0 = x0 * x0 + y0 * y0 + z0 * z0;
    float nq1 = x1 * x1 + y1 * y1 + z1 * z1;

    int A0 = INT_MAX, A1 = INT_MAX, A2 = INT_MAX;
    int B0 = INT_MAX, B1 = INT_MAX, B2 = INT_MAX;

    #pragma unroll 4
    for (int qd = 0; qd < SEGN / 4; qd++) {
        float4 pa = sP[4 * qd], pb = sP[4 * qd + 1];
        float4 pc = sP[4 * qd + 2], pe = sP[4 * qd + 3];
        float sa = fmaf(ax0, pa.x, fmaf(ay0, pa.y, fmaf(az0, pa.z, pa.w)));
        float sb = fmaf(ax0, pb.x, fmaf(ay0, pb.y, fmaf(az0, pb.z, pb.w)));
        float sc = fmaf(ax0, pc.x, fmaf(ay0, pc.y, fmaf(az0, pc.z, pc.w)));
        float se = fmaf(ax0, pe.x, fmaf(ay0, pe.y, fmaf(az0, pe.z, pe.w)));
        float m0 = fmaxf(fminf(fminf(sa, sb), fminf(sc, se)) + nq0, 0.f);
        kins3((int)((__float_as_uint(m0) & QMASK) | (unsigned)qd), A0, A1, A2);
        float ta = fmaf(ax1, pa.x, fmaf(ay1, pa.y, fmaf(az1, pa.z, pa.w)));
        float tb = fmaf(ax1, pb.x, fmaf(ay1, pb.y, fmaf(az1, pb.z, pb.w)));
        float tc = fmaf(ax1, pc.x, fmaf(ay1, pc.y, fmaf(az1, pc.z, pc.w)));
        float te = fmaf(ax1, pe.x, fmaf(ay1, pe.y, fmaf(az1, pe.z, pe.w)));
        float m1 = fmaxf(fminf(fminf(ta, tb), fminf(tc, te)) + nq1, 0.f);
        kins3((int)((__float_as_uint(m1) & QMASK) | (unsigned)qd), B0, B1, B2);
    }

    size_t o0 = (size_t)(b * SEG + seg) * N1 + q0;
    size_t o1 = (size_t)(b * SEG + seg) * N1 + q1;
    g_pk[o0] = make_uint4((unsigned)A0, (unsigned)A1, (unsigned)A2, 0u);
    g_pk[o1] = make_uint4((unsigned)B0, (unsigned)B1, (unsigned)B2, 0u);
}

// ------------------- K3: global top-3 quads + exact rescan -------------------
__global__ void knn_merge(const float* __restrict__ xyz1) {
    int t = blockIdx.x * blockDim.x + threadIdx.x;
    if (t >= BB * N1) return;
    int b = t / N1, q = t % N1;

    float D0 = 3.0e38f, D1 = 3.0e38f, D2 = 3.0e38f;
    int   G0 = 0, G1 = 0, G2 = 0;
    #pragma unroll
    for (int s = 0; s < SEG; s++) {
        uint4 k = g_pk[(size_t)(b * SEG + s) * N1 + q];
        unsigned kk[3] = {k.x, k.y, k.z};
        #pragma unroll
        for (int i = 0; i < 3; i++) {
            int gid = s * (SEGN / 4) + (int)(kk[i] & 127u);
            float d = __uint_as_float(kk[i] & QMASK);
            ins3(d, gid, D0, D1, D2, G0, G1, G2);
        }
    }

    float x = xyz1[3 * t], y = xyz1[3 * t + 1], z = xyz1[3 * t + 2];
    float nq = x * x + y * y + z * z;

    float A0 = 3.0e38f, A1 = 3.0e38f, A2 = 3.0e38f;
    int   I0 = 0, I1 = 0, I2 = 0;
    int gs[3] = {G0, G1, G2};
    #pragma unroll
    for (int i = 0; i < 3; i++) {
        int base = gs[i] * 4;
        #pragma unroll
        for (int c = 0; c < 4; c++) {
            float4 p = g_xyz2n[b * N2 + base + c];
            float d = nq + p.w - 2.f * (x * p.x + y * p.y + z * p.z);
            ins3(d, base + c, A0, A1, A2, I0, I1, I2);
        }
    }

    float w0 = 1.f / A0, w1 = 1.f / A1, w2 = 1.f / A2;
    float inv = 1.f / (w0 + w1 + w2);
    g_w4[t] = make_float4(w0 * inv, w1 * inv, w2 * inv, 0.f);
    g_i4[t] = make_int4(I0, I1, I2, 0);
}

// ------------------- MLP building blocks -------------------
// Per-warp W chunk stream: warp's own 16 oc rows x 32 k, dest tile [oc][k] stride 36.
__device__ __forceinline__ void issue_w(int c, int warp, int lane, float* sW) {
    const float* src; int Ksrc, kc;
    if (c < 12) { src = g_W0a; Ksrc = CIN; kc = c * 32; }
    else        { src = g_W1a; Ksrc = CH;  kc = (c - 12) * 32; }
    float* dst = sW + warp * (3 * WT) + (c % 3) * WT;
    int Rw = warp * 16;
    #pragma unroll
    for (int i = 0; i < 4; i++) {
        int idx = lane + 32 * i;            // 0..127 = 16 oc x 8 k-quads
        int ocl = idx >> 3, kq = idx & 7;
        cp16(dst + ocl * 36 + kq * 4, src + (size_t)(Rw + ocl) * Ksrc + kc + kq * 4);
    }
    CP_COMMIT();
}

// 1 m-tile (16 oc) x 8 n-tiles; A frags from per-warp stride-36 tile (conflict-free)
__device__ __forceinline__ void gemm_chunk(const float* wt, const float* sB,
                                           int lane, float acc[8][4]) {
    int grp = lane >> 2, tig = lane & 3;
    #pragma unroll
    for (int ks = 0; ks < 4; ks++) {
        int k8 = ks * 8;
        unsigned a[4], bf[8][2];
        const float* r0 = wt + grp * 36;
        const float* r8 = wt + (grp + 8) * 36;
        a[0] = __float_as_uint(r0[k8 + tig]);
        a[1] = __float_as_uint(r8[k8 + tig]);
        a[2] = __float_as_uint(r0[k8 + tig + 4]);
        a[3] = __float_as_uint(r8[k8 + tig + 4]);
        const float* x0r = sB + (k8 + tig) * SXS;
        const float* x4r = sB + (k8 + tig + 4) * SXS;
        #pragma unroll
        for (int j = 0; j < 8; j++) {
            int cb = j * 8 + grp;
            bf[j][0] = __float_as_uint(x0r[cb]);
            bf[j][1] = __float_as_uint(x4r[cb]);
        }
        #pragma unroll
        for (int j = 0; j < 8; j++)
            mma8(acc[j], a, bf[j]);
    }
}

// ------------------- K4: fused MLP + channel max (16 warps, warp-private W) -------------------
__global__ void __launch_bounds__(512, 1)
mlp_kernel(const float* __restrict__ points1, const float* __restrict__ pb1,
           float* __restrict__ out) {
    extern __shared__ float sm[];
    float* sX   = sm;                         // [384][SXS]; rows 0..255 reused as Y
    float* sW   = sm + SX_FLOATS;             // 16 warps x 3 bufs x WT
    int*   sOutI = (int*)(sm + SX_FLOATS + SW_TOT);

    int b  = blockIdx.y;
    int n0 = blockIdx.x * TN;
    int tid = threadIdx.x;
    int warp = tid >> 5, lane = tid & 31;
    int grp = lane >> 2, tig = lane & 3;
    int Rw = warp * 16;                       // warp's 16 oc rows

    // per-warp prefetch of first two W chunks
    issue_w(0, warp, lane, sW);
    issue_w(1, warp, lane, sW);

    // ---- Phase A: build X (384 x 64) ----
    for (int idx = tid; idx < CC * TN; idx += 512) {
        int c = idx >> 6, n = idx & 63;
        sX[c * SXS + n]         = cvt_tf32(points1[((size_t)b * CC + c) * N1 + n0 + n]);
        sX[(c + 256) * SXS + n] = cvt_tf32(pb1[((size_t)b * CC + c) * N1 + n0 + n]);
    }
    #pragma unroll
    for (int qq = 0; qq < 4; qq++) {
        int q = warp * 4 + qq;
        int n = n0 + q;
        float4 wv = g_w4[b * N1 + n];
        int4   iv = g_i4[b * N1 + n];
        const float* r0 = &g_p2t[((size_t)b * N2 + iv.x) * CC];
        const float* r1 = &g_p2t[((size_t)b * N2 + iv.y) * CC];
        const float* r2 = &g_p2t[((size_t)b * N2 + iv.z) * CC];
        #pragma unroll
        for (int i = 0; i < 4; i++) {
            int c = lane + 32 * i;
            float v = wv.x * r0[c] + wv.y * r1[c] + wv.z * r2[c];
            sX[(128 + c) * SXS + q] = cvt_tf32(v);
        }
    }
    __syncthreads();

    // ---- GEMM1: barrier-free, per-warp W pipeline over 12 chunks ----
    float acc[8][4];
    #pragma unroll
    for (int j = 0; j < 8; j++)
        #pragma unroll
        for (int e = 0; e < 4; e++) acc[j][e] = 0.f;

    for (int c = 0; c < 12; c++) {
        CPW1();
        issue_w(c + 2, warp, lane, sW);
        gemm_chunk(sW + warp * (3 * WT) + (c % 3) * WT, sX + c * 32 * SXS, lane, acc);
    }
    __syncthreads();   // all warps done reading X rows 0..255 before Y overwrites them

    // ---- epilogue 1: bias + ReLU -> Y (warp's own 16 rows) ----
    {
        float bz0 = g_b0f[Rw + grp];
        float bz1 = g_b0f[Rw + grp + 8];
        float* sY = sm;
        #pragma unroll
        for (int j = 0; j < 8; j++) {
            int col = 8 * j + 2 * tig;
            sY[(Rw + grp) * SXS + col]         = cvt_tf32(fmaxf(acc[j][0] + bz0, 0.f));
            sY[(Rw + grp) * SXS + col + 1]     = cvt_tf32(fmaxf(acc[j][1] + bz0, 0.f));
            sY[(Rw + grp + 8) * SXS + col]     = cvt_tf32(fmaxf(acc[j][2] + bz1, 0.f));
            sY[(Rw + grp + 8) * SXS + col + 1] = cvt_tf32(fmaxf(acc[j][3] + bz1, 0.f));
        }
    }
    __syncthreads();   // Y visible to all before GEMM2 reads

    // ---- GEMM2: barrier-free, chunks 12..19 ----
    float ac2[8][4];
    #pragma unroll
    for (int j = 0; j < 8; j++)
        #pragma unroll
        for (int e = 0; e < 4; e++) ac2[j][e] = 0.f;

    for (int c = 12; c < 20; c++) {
        if (c == 19) { CPW0(); } else { CPW1(); }
        if (c + 2 < 20) issue_w(c + 2, warp, lane, sW);
        gemm_chunk(sW + warp * (3 * WT) + (c % 3) * WT, sm + (c - 12) * 32 * SXS, lane, ac2);
    }

    // ---- epilogue 2: bias + ReLU + channel max ----
    float bb0 = g_b1f[Rw + grp];
    float bb1 = g_b1f[Rw + grp + 8];

    if (tid < TN) sOutI[tid] = 0;   // ReLU output >= 0 -> int 0 valid identity
    __syncthreads();

    #pragma unroll
    for (int j = 0; j < 8; j++) {
        #pragma unroll
        for (int e = 0; e < 2; e++) {
            int col = 8 * j + 2 * tig + e;
            float v =    fmaxf(ac2[j][e]     + bb0, 0.f);
            v = fmaxf(v, fmaxf(ac2[j][e + 2] + bb1, 0.f));
            v = fmaxf(v, __shfl_xor_sync(0xffffffffu, v, 4));
            v = fmaxf(v, __shfl_xor_sync(0xffffffffu, v, 8));
            v = fmaxf(v, __shfl_xor_sync(0xffffffffu, v, 16));
            if (grp == 0) atomicMax(&sOutI[col], __float_as_int(v));
        }
    }
    __syncthreads();
    if (tid < TN) out[(size_t)b * N1 + n0 + tid] = __int_as_float(sOutI[tid]);
}

// ------------------- launch -------------------
extern "C" void kernel_launch(void* const* d_in, const int* in_sizes, int n_in,
                              void* d_out, int out_size) {
    const float* xyz1    = (const float*)d_in[0];
    const float* xyz2    = (const float*)d_in[1];
    const float* points2 = (const float*)d_in[2];
    const float* points1 = (const float*)d_in[3];
    const float* pb1     = (const float*)d_in[4];
    const float* w0  = (const float*)d_in[5];
    const float* b0  = (const float*)d_in[6];
    const float* g0  = (const float*)d_in[7];
    const float* be0 = (const float*)d_in[8];
    const float* m0  = (const float*)d_in[9];
    const float* v0  = (const float*)d_in[10];
    const float* w1  = (const float*)d_in[11];
    const float* b1  = (const float*)d_in[12];
    const float* g1  = (const float*)d_in[13];
    const float* be1 = (const float*)d_in[14];
    const float* m1  = (const float*)d_in[15];
    const float* v1  = (const float*)d_in[16];
    float* out = (float*)d_out;

    cudaFuncSetAttribute(mlp_kernel, cudaFuncAttributeMaxDynamicSharedMemorySize,
                         SMEM_MLP_BYTES);

    prep_kernel<<<PREP_END, 256>>>(points2, xyz2,
                                   w0, b0, g0, be0, m0, v0,
                                   w1, b1, g1, be1, m1, v1);
    knn_part<<<dim3(N1 / 512, SEG, BB), 256>>>(xyz1);
    knn_merge<<<(BB * N1 + 255) / 256, 256>>>(xyz1);
    mlp_kernel<<<dim3(N1 / TN, BB), 512, SMEM_MLP_BYTES>>>(points1, pb1, out);
}

// round 15
// speedup vs baseline: 1.2416x; 1.2416x over previous
#include <cuda_runtime.h>
#include <cuda_fp16.h>
#include <cstdint>
#include <climits>

#define BB   4
#define N1   16384
#define N2   4096
#define CC   128
#define CIN  384
#define CH   256
#define TN   64
#define SEG  8
#define SEGN (N2 / SEG)          // 512 candidates, 128 quads per segment
#define QMASK 0xFFFFFF80u

// ---- fp16 MLP smem layout (32-bit words) ----
#define SXW   72                 // X/Y row stride in half2 words: bank-clean (8*tig+grp)
#define NKP   192                // 384 k / 2
#define WTU   640                // per-warp per-buffer W tile: 32 oc x 20 words (16 used + pad)
#define SX_U  (NKP * SXW)        // 13824 words
#define SW_U  (8 * 3 * WTU)      // 15360 words
#define SMEM_MLP_BYTES ((SX_U + SW_U + 64) * 4)   // 116992

// prep_kernel grid partition
#define PREP_T0   2048
#define PREP_F0   (PREP_T0 + 384)
#define PREP_END  (PREP_F0 + 64)

// ------------------- scratch -------------------
__device__ float4 g_xyz2n[BB * N2];
__device__ uint4  g_pk[BB * SEG * N1];
__device__ float4 g_w4[BB * N1];
__device__ int4   g_i4[BB * N1];
__device__ float  g_p2t[BB * N2 * CC];
__device__ __half g_W0h[CH * CIN];           // folded W0 (oc, k) row-major, fp16
__device__ __half g_W1h[CH * CH];            // folded W1 (oc, k) row-major, fp16
__device__ float  g_b0f[CH];
__device__ float  g_b1f[CH];

// ------------------- helpers -------------------
__device__ __forceinline__ void mma16(float* d, const unsigned* a, const unsigned* b) {
    asm("mma.sync.aligned.m16n8k16.row.col.f32.f16.f16.f32 "
        "{%0,%1,%2,%3}, {%4,%5,%6,%7}, {%8,%9}, {%0,%1,%2,%3};\n"
        : "+f"(d[0]), "+f"(d[1]), "+f"(d[2]), "+f"(d[3])
        : "r"(a[0]), "r"(a[1]), "r"(a[2]), "r"(a[3]), "r"(b[0]), "r"(b[1]));
}

__device__ __forceinline__ void cp16(void* s, const void* g) {
    unsigned sa = (unsigned)__cvta_generic_to_shared(s);
    asm volatile("cp.async.cg.shared.global [%0], [%1], 16;\n" :: "r"(sa), "l"(g));
}
#define CP_COMMIT() asm volatile("cp.async.commit_group;\n")
#define CPW1() asm volatile("cp.async.wait_group 1;\n")
#define CPW0() asm volatile("cp.async.wait_group 0;\n")

// sorted-3 insert over signed-int keys (5 min/max)
__device__ __forceinline__ void kins3(int k, int& K0, int& K1, int& K2) {
    int t0 = min(K0, k), u0 = max(K0, k);
    int t1 = min(K1, u0), u1 = max(K1, u0);
    K2 = min(K2, u1); K0 = t0; K1 = t1;
}
__device__ __forceinline__ void ins3(float s, int j,
                                     float& a0, float& a1, float& a2,
                                     int& i0, int& i1, int& i2) {
    if (s < a2) {
        if (s < a1) {
            a2 = a1; i2 = i1;
            if (s < a0) { a1 = a0; i1 = i0; a0 = s; i0 = j; }
            else        { a1 = s;  i1 = j; }
        } else { a2 = s; i2 = j; }
    }
}

// ------------------- K1: fused prep (transpose + fold + pack) -------------------
__global__ void __launch_bounds__(256) prep_kernel(
    const float* __restrict__ p2, const float* __restrict__ xyz2,
    const float* __restrict__ w0, const float* __restrict__ b0,
    const float* __restrict__ g0, const float* __restrict__ be0,
    const float* __restrict__ m0, const float* __restrict__ v0,
    const float* __restrict__ w1, const float* __restrict__ b1,
    const float* __restrict__ g1, const float* __restrict__ be1,
    const float* __restrict__ m1, const float* __restrict__ v1) {
    __shared__ float tile[32][33];
    int blk = blockIdx.x;
    int tid = threadIdx.x;

    if (blk < PREP_T0) {
        int b = blk >> 9;
        int rem = blk & 511;
        int cb = (rem >> 7) * 32;
        int nb = (rem & 127) * 32;
        int tx = tid & 31, ty = tid >> 5;
        #pragma unroll
        for (int i = 0; i < 32; i += 8)
            tile[ty + i][tx] = p2[((size_t)b * CC + cb + ty + i) * N2 + nb + tx];
        __syncthreads();
        #pragma unroll
        for (int i = 0; i < 32; i += 8)
            g_p2t[((size_t)b * N2 + nb + ty + i) * CC + cb + tx] = tile[tx][ty + i];
    } else if (blk < PREP_F0) {
        int t = (blk - PREP_T0) * 256 + tid;
        if (t < CH * CIN) {
            int o = t / CIN;
            float s = g0[o] * rsqrtf(v0[o] + 1e-5f);
            g_W0h[t] = __float2half_rn(w0[t] * s);
        }
        if (t < CH * CH) {
            int o = t / CH;
            float s = g1[o] * rsqrtf(v1[o] + 1e-5f);
            g_W1h[t] = __float2half_rn(w1[t] * s);
        }
        if (t < CH) {
            float s0 = g0[t] * rsqrtf(v0[t] + 1e-5f);
            g_b0f[t] = (b0[t] - m0[t]) * s0 + be0[t];
            float s1 = g1[t] * rsqrtf(v1[t] + 1e-5f);
            g_b1f[t] = (b1[t] - m1[t]) * s1 + be1[t];
        }
    } else {
        int t = (blk - PREP_F0) * 256 + tid;
        if (t < BB * N2) {
            float x = xyz2[3 * t], y = xyz2[3 * t + 1], z = xyz2[3 * t + 2];
            g_xyz2n[t] = make_float4(x, y, z, x * x + y * y + z * z);
        }
    }
}

// ------------------- K2: quad-min 3-NN scan (SEG=8) -------------------
__global__ void __launch_bounds__(256) knn_part(const float* __restrict__ xyz1) {
    __shared__ float4 sP[SEGN];      // 8 KB
    int b = blockIdx.z, seg = blockIdx.y;
    int t = threadIdx.x;
    for (int i = t; i < SEGN; i += 256) sP[i] = g_xyz2n[b * N2 + seg * SEGN + i];
    __syncthreads();

    int q0 = blockIdx.x * 512 + t, q1 = q0 + 256;
    const float* p0 = xyz1 + ((size_t)b * N1 + q0) * 3;
    const float* p1 = xyz1 + ((size_t)b * N1 + q1) * 3;
    float x0 = p0[0], y0 = p0[1], z0 = p0[2];
    float x1 = p1[0], y1 = p1[1], z1 = p1[2];
    float ax0 = -2.f * x0, ay0 = -2.f * y0, az0 = -2.f * z0;
    float ax1 = -2.f * x1, ay1 = -2.f * y1, az1 = -2.f * z1;
    float nq0 = x0 * x0 + y0 * y0 + z0 * z0;
    float nq1 = x1 * x1 + y1 * y1 + z1 * z1;

    int A0 = INT_MAX, A1 = INT_MAX, A2 = INT_MAX;
    int B0 = INT_MAX, B1 = INT_MAX, B2 = INT_MAX;

    #pragma unroll 4
    for (int qd = 0; qd < SEGN / 4; qd++) {
        float4 pa = sP[4 * qd], pb = sP[4 * qd + 1];
        float4 pc = sP[4 * qd + 2], pe = sP[4 * qd + 3];
        float sa = fmaf(ax0, pa.x, fmaf(ay0, pa.y, fmaf(az0, pa.z, pa.w)));
        float sb = fmaf(ax0, pb.x, fmaf(ay0, pb.y, fmaf(az0, pb.z, pb.w)));
        float sc = fmaf(ax0, pc.x, fmaf(ay0, pc.y, fmaf(az0, pc.z, pc.w)));
        float se = fmaf(ax0, pe.x, fmaf(ay0, pe.y, fmaf(az0, pe.z, pe.w)));
        float m0 = fmaxf(fminf(fminf(sa, sb), fminf(sc, se)) + nq0, 0.f);
        kins3((int)((__float_as_uint(m0) & QMASK) | (unsigned)qd), A0, A1, A2);
        float ta = fmaf(ax1, pa.x, fmaf(ay1, pa.y, fmaf(az1, pa.z, pa.w)));
        float tb = fmaf(ax1, pb.x, fmaf(ay1, pb.y, fmaf(az1, pb.z, pb.w)));
        float tc = fmaf(ax1, pc.x, fmaf(ay1, pc.y, fmaf(az1, pc.z, pc.w)));
        float te = fmaf(ax1, pe.x, fmaf(ay1, pe.y, fmaf(az1, pe.z, pe.w)));
        float m1 = fmaxf(fminf(fminf(ta, tb), fminf(tc, te)) + nq1, 0.f);
        kins3((int)((__float_as_uint(m1) & QMASK) | (unsigned)qd), B0, B1, B2);
    }

    size_t o0 = (size_t)(b * SEG + seg) * N1 + q0;
    size_t o1 = (size_t)(b * SEG + seg) * N1 + q1;
    g_pk[o0] = make_uint4((unsigned)A0, (unsigned)A1, (unsigned)A2, 0u);
    g_pk[o1] = make_uint4((unsigned)B0, (unsigned)B1, (unsigned)B2, 0u);
}

// ------------------- K3: global top-3 quads + exact rescan -------------------
__global__ void knn_merge(const float* __restrict__ xyz1) {
    int t = blockIdx.x * blockDim.x + threadIdx.x;
    if (t >= BB * N1) return;
    int b = t / N1, q = t % N1;

    float D0 = 3.0e38f, D1 = 3.0e38f, D2 = 3.0e38f;
    int   G0 = 0, G1 = 0, G2 = 0;
    #pragma unroll
    for (int s = 0; s < SEG; s++) {
        uint4 k = g_pk[(size_t)(b * SEG + s) * N1 + q];
        unsigned kk[3] = {k.x, k.y, k.z};
        #pragma unroll
        for (int i = 0; i < 3; i++) {
            int gid = s * (SEGN / 4) + (int)(kk[i] & 127u);
            float d = __uint_as_float(kk[i] & QMASK);
            ins3(d, gid, D0, D1, D2, G0, G1, G2);
        }
    }

    float x = xyz1[3 * t], y = xyz1[3 * t + 1], z = xyz1[3 * t + 2];
    float nq = x * x + y * y + z * z;

    float A0 = 3.0e38f, A1 = 3.0e38f, A2 = 3.0e38f;
    int   I0 = 0, I1 = 0, I2 = 0;
    int gs[3] = {G0, G1, G2};
    #pragma unroll
    for (int i = 0; i < 3; i++) {
        int base = gs[i] * 4;
        #pragma unroll
        for (int c = 0; c < 4; c++) {
            float4 p = g_xyz2n[b * N2 + base + c];
            float d = nq + p.w - 2.f * (x * p.x + y * p.y + z * p.z);
            ins3(d, base + c, A0, A1, A2, I0, I1, I2);
        }
    }

    float w0 = 1.f / A0, w1 = 1.f / A1, w2 = 1.f / A2;
    float inv = 1.f / (w0 + w1 + w2);
    g_w4[t] = make_float4(w0 * inv, w1 * inv, w2 * inv, 0.f);
    g_i4[t] = make_int4(I0, I1, I2, 0);
}

// ------------------- MLP building blocks (fp16 m16n8k16) -------------------
// Per-warp W chunk: 32 oc x 32 k halves -> tile [oc][kp] stride 20 words.
__device__ __forceinline__ void issue_w(int c, int warp, int lane, unsigned* sW) {
    const __half* src; int Ksrc, kc;
    if (c < 12) { src = g_W0h; Ksrc = CIN; kc = c * 32; }
    else        { src = g_W1h; Ksrc = CH;  kc = (c - 12) * 32; }
    unsigned* dst = sW + warp * (3 * WTU) + (c % 3) * WTU;
    int Rw = warp * 32;
    #pragma unroll
    for (int i = 0; i < 4; i++) {
        int idx = lane + 32 * i;            // 0..127 = 32 oc x 4 k-octs
        int ocl = idx >> 2, kq = idx & 3;
        cp16(dst + ocl * 20 + kq * 4, src + (size_t)(Rw + ocl) * Ksrc + kc + kq * 8);
    }
    CP_COMMIT();
}

// 2 m-tiles (32 oc) x 8 n-tiles, 2 k16-steps per 32-k chunk
__device__ __forceinline__ void gemm_chunk(const unsigned* wt, const unsigned* sB,
                                           int lane, float acc[2][8][4]) {
    int grp = lane >> 2, tig = lane & 3;
    #pragma unroll
    for (int ks = 0; ks < 2; ks++) {
        int kp8 = ks * 8;
        unsigned a[2][4], bf[8][2];
        #pragma unroll
        for (int m = 0; m < 2; m++) {
            const unsigned* r0 = wt + (m * 16 + grp) * 20 + kp8;
            const unsigned* r8 = wt + (m * 16 + grp + 8) * 20 + kp8;
            a[m][0] = r0[tig];
            a[m][1] = r8[tig];
            a[m][2] = r0[tig + 4];
            a[m][3] = r8[tig + 4];
        }
        const unsigned* x0r = sB + (kp8 + tig) * SXW;
        const unsigned* x4r = sB + (kp8 + tig + 4) * SXW;
        #pragma unroll
        for (int j = 0; j < 8; j++) {
            int cb = j * 8 + grp;
            bf[j][0] = x0r[cb];
            bf[j][1] = x4r[cb];
        }
        #pragma unroll
        for (int m = 0; m < 2; m++)
            #pragma unroll
            for (int j = 0; j < 8; j++)
                mma16(acc[m][j], a[m], bf[j]);
    }
}

// ------------------- K4: fused MLP (fp16) + channel max -------------------
__global__ void __launch_bounds__(256, 1)
mlp_kernel(const float* __restrict__ points1, const float* __restrict__ pb1,
           float* __restrict__ out) {
    extern __shared__ unsigned sm32[];
    __half2* sX2  = (__half2*)sm32;           // [192 kp][SXW]; kp 0..127 reused as Y
    __half*  sYh  = (__half*)sm32;
    unsigned* sW  = sm32 + SX_U;              // 8 warps x 3 bufs x WTU
    int*     sOutI = (int*)(sm32 + SX_U + SW_U);

    int b  = blockIdx.y;
    int n0 = blockIdx.x * TN;
    int tid = threadIdx.x;
    int warp = tid >> 5, lane = tid & 31;
    int grp = lane >> 2, tig = lane & 3;
    int Rw = warp * 32;

    issue_w(0, warp, lane, sW);
    issue_w(1, warp, lane, sW);

    // ---- Phase A: build X as half2 words [kp][n] ----
    for (int idx = tid; idx < 64 * TN; idx += 256) {
        int kp = idx >> 6, n = idx & 63;      // kp 0..63 (k 0..127), pb1 -> kp 128..191
        const float* p1r = points1 + ((size_t)b * CC + 2 * kp) * N1 + n0 + n;
        sX2[kp * SXW + n] = __floats2half2_rn(p1r[0], p1r[N1]);
        const float* pbr = pb1 + ((size_t)b * CC + 2 * kp) * N1 + n0 + n;
        sX2[(128 + kp) * SXW + n] = __floats2half2_rn(pbr[0], pbr[N1]);
    }
    // fused section: kp 64..127 (k 128..255)
    for (int qq = 0; qq < 8; qq++) {
        int q = warp * 8 + qq;
        int n = n0 + q;
        float4 wv = g_w4[b * N1 + n];
        int4   iv = g_i4[b * N1 + n];
        const float2* r0 = (const float2*)&g_p2t[((size_t)b * N2 + iv.x) * CC];
        const float2* r1 = (const float2*)&g_p2t[((size_t)b * N2 + iv.y) * CC];
        const float2* r2 = (const float2*)&g_p2t[((size_t)b * N2 + iv.z) * CC];
        #pragma unroll
        for (int i = 0; i < 2; i++) {
            int cp = lane + 32 * i;           // channel-pair 0..63
            float2 e0 = r0[cp], e1 = r1[cp], e2 = r2[cp];
            float vx = wv.x * e0.x + wv.y * e1.x + wv.z * e2.x;
            float vy = wv.x * e0.y + wv.y * e1.y + wv.z * e2.y;
            sX2[(64 + cp) * SXW + q] = __floats2half2_rn(vx, vy);
        }
    }
    __syncthreads();

    // ---- GEMM1: barrier-free per-warp W pipeline, 12 chunks ----
    float acc[2][8][4];
    #pragma unroll
    for (int m = 0; m < 2; m++)
        #pragma unroll
        for (int j = 0; j < 8; j++)
            #pragma unroll
            for (int e = 0; e < 4; e++) acc[m][j][e] = 0.f;

    for (int c = 0; c < 12; c++) {
        CPW1();
        issue_w(c + 2, warp, lane, sW);
        gemm_chunk(sW + warp * (3 * WTU) + (c % 3) * WTU, sm32 + c * 16 * SXW, lane, acc);
    }
    __syncthreads();   // all warps done reading X kp 0..127 before Y overwrites

    // ---- epilogue 1: bias + ReLU -> Y halves (warp's own 32 oc rows) ----
    {
        float bz[4];
        #pragma unroll
        for (int i = 0; i < 4; i++) bz[i] = g_b0f[Rw + grp + 8 * i];
        #pragma unroll
        for (int m = 0; m < 2; m++)
            #pragma unroll
            for (int j = 0; j < 8; j++) {
                int oc0 = Rw + 16 * m + grp;
                int oc1 = oc0 + 8;
                int col = 8 * j + 2 * tig;
                float v00 = fmaxf(acc[m][j][0] + bz[2 * m], 0.f);
                float v01 = fmaxf(acc[m][j][1] + bz[2 * m], 0.f);
                float v10 = fmaxf(acc[m][j][2] + bz[2 * m + 1], 0.f);
                float v11 = fmaxf(acc[m][j][3] + bz[2 * m + 1], 0.f);
                int h0 = (oc0 >> 1) * (2 * SXW) + (oc0 & 1);
                int h1 = (oc1 >> 1) * (2 * SXW) + (oc1 & 1);
                sYh[h0 + 2 * col]       = __float2half_rn(v00);
                sYh[h0 + 2 * (col + 1)] = __float2half_rn(v01);
                sYh[h1 + 2 * col]       = __float2half_rn(v10);
                sYh[h1 + 2 * (col + 1)] = __float2half_rn(v11);
            }
    }
    __syncthreads();   // Y visible to all before GEMM2 reads

    // ---- GEMM2: chunks 12..19 over Y (kp 0..127) ----
    float ac2[2][8][4];
    #pragma unroll
    for (int m = 0; m < 2; m++)
        #pragma unroll
        for (int j = 0; j < 8; j++)
            #pragma unroll
            for (int e = 0; e < 4; e++) ac2[m][j][e] = 0.f;

    for (int c = 12; c < 20; c++) {
        if (c == 19) { CPW0(); } else { CPW1(); }
        if (c + 2 < 20) issue_w(c + 2, warp, lane, sW);
        gemm_chunk(sW + warp * (3 * WTU) + (c % 3) * WTU,
                   sm32 + (c - 12) * 16 * SXW, lane, ac2);
    }

    // ---- epilogue 2: bias + ReLU + channel max ----
    float bz1[4];
    #pragma unroll
    for (int i = 0; i < 4; i++) bz1[i] = g_b1f[Rw + grp + 8 * i];

    if (tid < TN) sOutI[tid] = 0;   // ReLU output >= 0 -> int 0 valid identity
    __syncthreads();

    #pragma unroll
    for (int j = 0; j < 8; j++) {
        #pragma unroll
        for (int e = 0; e < 2; e++) {
            int col = 8 * j + 2 * tig + e;
            float v =    fmaxf(ac2[0][j][e]     + bz1[0], 0.f);
            v = fmaxf(v, fmaxf(ac2[0][j][e + 2] + bz1[1], 0.f));
            v = fmaxf(v, fmaxf(ac2[1][j][e]     + bz1[2], 0.f));
            v = fmaxf(v, fmaxf(ac2[1][j][e + 2] + bz1[3], 0.f));
            v = fmaxf(v, __shfl_xor_sync(0xffffffffu, v, 4));
            v = fmaxf(v, __shfl_xor_sync(0xffffffffu, v, 8));
            v = fmaxf(v, __shfl_xor_sync(0xffffffffu, v, 16));
            if (grp == 0) atomicMax(&sOutI[col], __float_as_int(v));
        }
    }
    __syncthreads();
    if (tid < TN) out[(size_t)b * N1 + n0 + tid] = __int_as_float(sOutI[tid]);
}

// ------------------- launch -------------------
extern "C" void kernel_launch(void* const* d_in, const int* in_sizes, int n_in,
                              void* d_out, int out_size) {
    const float* xyz1    = (const float*)d_in[0];
    const float* xyz2    = (const float*)d_in[1];
    const float* points2 = (const float*)d_in[2];
    const float* points1 = (const float*)d_in[3];
    const float* pb1     = (const float*)d_in[4];
    const float* w0  = (const float*)d_in[5];
    const float* b0  = (const float*)d_in[6];
    const float* g0  = (const float*)d_in[7];
    const float* be0 = (const float*)d_in[8];
    const float* m0  = (const float*)d_in[9];
    const float* v0  = (const float*)d_in[10];
    const float* w1  = (const float*)d_in[11];
    const float* b1  = (const float*)d_in[12];
    const float* g1  = (const float*)d_in[13];
    const float* be1 = (const float*)d_in[14];
    const float* m1  = (const float*)d_in[15];
    const float* v1  = (const float*)d_in[16];
    float* out = (float*)d_out;

    cudaFuncSetAttribute(mlp_kernel, cudaFuncAttributeMaxDynamicSharedMemorySize,
                         SMEM_MLP_BYTES);

    prep_kernel<<<PREP_END, 256>>>(points2, xyz2,
                                   w0, b0, g0, be0, m0, v0,
                                   w1, b1, g1, be1, m1, v1);
    knn_part<<<dim3(N1 / 512, SEG, BB), 256>>>(xyz1);
    knn_merge<<<(BB * N1 + 255) / 256, 256>>>(xyz1);
    mlp_kernel<<<dim3(N1 / TN, BB), 256, SMEM_MLP_BYTES>>>(points1, pb1, out);
}

// round 16
// speedup vs baseline: 1.4888x; 1.1991x over previous
#include <cuda_runtime.h>
#include <cuda_fp16.h>
#include <cstdint>
#include <climits>

#define BB   4
#define N1   16384
#define N2   4096
#define CC   128
#define CIN  384
#define CH   256
#define TN   128
#define SEG  8
#define SEGN (N2 / SEG)          // 512 candidates, 128 quads per segment
#define QMASK 0xFFFFFF80u

// ---- fp16 MLP smem layout (32-bit words) ----
#define SXW   136                // X/Y row stride in half2 words: 136 % 32 == 8 -> bank-clean
#define NKP   192                // 384 k / 2
#define WTU   640                // per-warp per-buffer W tile: 32 oc x 20 words
#define SX_U  (NKP * SXW)        // 26112 words
#define SW_U  (8 * 3 * WTU)      // 15360 words
#define SMEM_MLP_BYTES ((SX_U + SW_U + 160) * 4)   // 166528

// prep_kernel grid partition
#define PREP_T0   2048
#define PREP_F0   (PREP_T0 + 384)
#define PREP_END  (PREP_F0 + 64)

// ------------------- scratch -------------------
__device__ float4 g_xyz2n[BB * N2];
__device__ uint4  g_pk[BB * SEG * N1];
__device__ float4 g_w4[BB * N1];
__device__ int4   g_i4[BB * N1];
__device__ float  g_p2t[BB * N2 * CC];
__device__ __half g_W0h[CH * CIN];           // folded W0 (oc, k) row-major, fp16
__device__ __half g_W1h[CH * CH];            // folded W1 (oc, k) row-major, fp16
__device__ float  g_b0f[CH];
__device__ float  g_b1f[CH];

// ------------------- helpers -------------------
__device__ __forceinline__ void mma16(float* d, const unsigned* a, const unsigned* b) {
    asm("mma.sync.aligned.m16n8k16.row.col.f32.f16.f16.f32 "
        "{%0,%1,%2,%3}, {%4,%5,%6,%7}, {%8,%9}, {%0,%1,%2,%3};\n"
        : "+f"(d[0]), "+f"(d[1]), "+f"(d[2]), "+f"(d[3])
        : "r"(a[0]), "r"(a[1]), "r"(a[2]), "r"(a[3]), "r"(b[0]), "r"(b[1]));
}

__device__ __forceinline__ void cp16(void* s, const void* g) {
    unsigned sa = (unsigned)__cvta_generic_to_shared(s);
    asm volatile("cp.async.cg.shared.global [%0], [%1], 16;\n" :: "r"(sa), "l"(g));
}
#define CP_COMMIT() asm volatile("cp.async.commit_group;\n")
#define CPW1() asm volatile("cp.async.wait_group 1;\n")
#define CPW0() asm volatile("cp.async.wait_group 0;\n")

// sorted-3 insert over signed-int keys (5 min/max)
__device__ __forceinline__ void kins3(int k, int& K0, int& K1, int& K2) {
    int t0 = min(K0, k), u0 = max(K0, k);
    int t1 = min(K1, u0), u1 = max(K1, u0);
    K2 = min(K2, u1); K0 = t0; K1 = t1;
}
__device__ __forceinline__ void ins3(float s, int j,
                                     float& a0, float& a1, float& a2,
                                     int& i0, int& i1, int& i2) {
    if (s < a2) {
        if (s < a1) {
            a2 = a1; i2 = i1;
            if (s < a0) { a1 = a0; i1 = i0; a0 = s; i0 = j; }
            else        { a1 = s;  i1 = j; }
        } else { a2 = s; i2 = j; }
    }
}

// ------------------- K1: fused prep (transpose + fold + pack) -------------------
__global__ void __launch_bounds__(256) prep_kernel(
    const float* __restrict__ p2, const float* __restrict__ xyz2,
    const float* __restrict__ w0, const float* __restrict__ b0,
    const float* __restrict__ g0, const float* __restrict__ be0,
    const float* __restrict__ m0, const float* __restrict__ v0,
    const float* __restrict__ w1, const float* __restrict__ b1,
    const float* __restrict__ g1, const float* __restrict__ be1,
    const float* __restrict__ m1, const float* __restrict__ v1) {
    __shared__ float tile[32][33];
    int blk = blockIdx.x;
    int tid = threadIdx.x;

    if (blk < PREP_T0) {
        int b = blk >> 9;
        int rem = blk & 511;
        int cb = (rem >> 7) * 32;
        int nb = (rem & 127) * 32;
        int tx = tid & 31, ty = tid >> 5;
        #pragma unroll
        for (int i = 0; i < 32; i += 8)
            tile[ty + i][tx] = p2[((size_t)b * CC + cb + ty + i) * N2 + nb + tx];
        __syncthreads();
        #pragma unroll
        for (int i = 0; i < 32; i += 8)
            g_p2t[((size_t)b * N2 + nb + ty + i) * CC + cb + tx] = tile[tx][ty + i];
    } else if (blk < PREP_F0) {
        int t = (blk - PREP_T0) * 256 + tid;
        if (t < CH * CIN) {
            int o = t / CIN;
            float s = g0[o] * rsqrtf(v0[o] + 1e-5f);
            g_W0h[t] = __float2half_rn(w0[t] * s);
        }
        if (t < CH * CH) {
            int o = t / CH;
            float s = g1[o] * rsqrtf(v1[o] + 1e-5f);
            g_W1h[t] = __float2half_rn(w1[t] * s);
        }
        if (t < CH) {
            float s0 = g0[t] * rsqrtf(v0[t] + 1e-5f);
            g_b0f[t] = (b0[t] - m0[t]) * s0 + be0[t];
            float s1 = g1[t] * rsqrtf(v1[t] + 1e-5f);
            g_b1f[t] = (b1[t] - m1[t]) * s1 + be1[t];
        }
    } else {
        int t = (blk - PREP_F0) * 256 + tid;
        if (t < BB * N2) {
            float x = xyz2[3 * t], y = xyz2[3 * t + 1], z = xyz2[3 * t + 2];
            g_xyz2n[t] = make_float4(x, y, z, x * x + y * y + z * z);
        }
    }
}

// ------------------- K2: quad-min 3-NN scan (SEG=8) -------------------
__global__ void __launch_bounds__(256) knn_part(const float* __restrict__ xyz1) {
    __shared__ float4 sP[SEGN];      // 8 KB
    int b = blockIdx.z, seg = blockIdx.y;
    int t = threadIdx.x;
    for (int i = t; i < SEGN; i += 256) sP[i] = g_xyz2n[b * N2 + seg * SEGN + i];
    __syncthreads();

    int q0 = blockIdx.x * 512 + t, q1 = q0 + 256;
    const float* p0 = xyz1 + ((size_t)b * N1 + q0) * 3;
    const float* p1 = xyz1 + ((size_t)b * N1 + q1) * 3;
    float x0 = p0[0], y0 = p0[1], z0 = p0[2];
    float x1 = p1[0], y1 = p1[1], z1 = p1[2];
    float ax0 = -2.f * x0, ay0 = -2.f * y0, az0 = -2.f * z0;
    float ax1 = -2.f * x1, ay1 = -2.f * y1, az1 = -2.f * z1;
    float nq0 = x0 * x0 + y0 * y0 + z0 * z0;
    float nq1 = x1 * x1 + y1 * y1 + z1 * z1;

    int A0 = INT_MAX, A1 = INT_MAX, A2 = INT_MAX;
    int B0 = INT_MAX, B1 = INT_MAX, B2 = INT_MAX;

    #pragma unroll 4
    for (int qd = 0; qd < SEGN / 4; qd++) {
        float4 pa = sP[4 * qd], pb = sP[4 * qd + 1];
        float4 pc = sP[4 * qd + 2], pe = sP[4 * qd + 3];
        float sa = fmaf(ax0, pa.x, fmaf(ay0, pa.y, fmaf(az0, pa.z, pa.w)));
        float sb = fmaf(ax0, pb.x, fmaf(ay0, pb.y, fmaf(az0, pb.z, pb.w)));
        float sc = fmaf(ax0, pc.x, fmaf(ay0, pc.y, fmaf(az0, pc.z, pc.w)));
        float se = fmaf(ax0, pe.x, fmaf(ay0, pe.y, fmaf(az0, pe.z, pe.w)));
        float m0 = fmaxf(fminf(fminf(sa, sb), fminf(sc, se)) + nq0, 0.f);
        kins3((int)((__float_as_uint(m0) & QMASK) | (unsigned)qd), A0, A1, A2);
        float ta = fmaf(ax1, pa.x, fmaf(ay1, pa.y, fmaf(az1, pa.z, pa.w)));
        float tb = fmaf(ax1, pb.x, fmaf(ay1, pb.y, fmaf(az1, pb.z, pb.w)));
        float tc = fmaf(ax1, pc.x, fmaf(ay1, pc.y, fmaf(az1, pc.z, pc.w)));
        float te = fmaf(ax1, pe.x, fmaf(ay1, pe.y, fmaf(az1, pe.z, pe.w)));
        float m1 = fmaxf(fminf(fminf(ta, tb), fminf(tc, te)) + nq1, 0.f);
        kins3((int)((__float_as_uint(m1) & QMASK) | (unsigned)qd), B0, B1, B2);
    }

    size_t o0 = (size_t)(b * SEG + seg) * N1 + q0;
    size_t o1 = (size_t)(b * SEG + seg) * N1 + q1;
    g_pk[o0] = make_uint4((unsigned)A0, (unsigned)A1, (unsigned)A2, 0u);
    g_pk[o1] = make_uint4((unsigned)B0, (unsigned)B1, (unsigned)B2, 0u);
}

// ------------------- K3: global top-3 quads + exact rescan -------------------
__global__ void knn_merge(const float* __restrict__ xyz1) {
    int t = blockIdx.x * blockDim.x + threadIdx.x;
    if (t >= BB * N1) return;
    int b = t / N1, q = t % N1;

    float D0 = 3.0e38f, D1 = 3.0e38f, D2 = 3.0e38f;
    int   G0 = 0, G1 = 0, G2 = 0;
    #pragma unroll
    for (int s = 0; s < SEG; s++) {
        uint4 k = g_pk[(size_t)(b * SEG + s) * N1 + q];
        unsigned kk[3] = {k.x, k.y, k.z};
        #pragma unroll
        for (int i = 0; i < 3; i++) {
            int gid = s * (SEGN / 4) + (int)(kk[i] & 127u);
            float d = __uint_as_float(kk[i] & QMASK);
            ins3(d, gid, D0, D1, D2, G0, G1, G2);
        }
    }

    float x = xyz1[3 * t], y = xyz1[3 * t + 1], z = xyz1[3 * t + 2];
    float nq = x * x + y * y + z * z;

    float A0 = 3.0e38f, A1 = 3.0e38f, A2 = 3.0e38f;
    int   I0 = 0, I1 = 0, I2 = 0;
    int gs[3] = {G0, G1, G2};
    #pragma unroll
    for (int i = 0; i < 3; i++) {
        int base = gs[i] * 4;
        #pragma unroll
        for (int c = 0; c < 4; c++) {
            float4 p = g_xyz2n[b * N2 + base + c];
            float d = nq + p.w - 2.f * (x * p.x + y * p.y + z * p.z);
            ins3(d, base + c, A0, A1, A2, I0, I1, I2);
        }
    }

    float w0 = 1.f / A0, w1 = 1.f / A1, w2 = 1.f / A2;
    float inv = 1.f / (w0 + w1 + w2);
    g_w4[t] = make_float4(w0 * inv, w1 * inv, w2 * inv, 0.f);
    g_i4[t] = make_int4(I0, I1, I2, 0);
}

// ------------------- MLP building blocks (fp16 m16n8k16, TN=128) -------------------
// Per-warp W chunk: 32 oc x 32 k halves -> tile [oc][kp] stride 20 words.
__device__ __forceinline__ void issue_w(int c, int warp, int lane, unsigned* sW) {
    const __half* src; int Ksrc, kc;
    if (c < 12) { src = g_W0h; Ksrc = CIN; kc = c * 32; }
    else        { src = g_W1h; Ksrc = CH;  kc = (c - 12) * 32; }
    unsigned* dst = sW + warp * (3 * WTU) + (c % 3) * WTU;
    int Rw = warp * 32;
    #pragma unroll
    for (int i = 0; i < 4; i++) {
        int idx = lane + 32 * i;            // 0..127 = 32 oc x 4 k-octs
        int ocl = idx >> 2, kq = idx & 3;
        cp16(dst + ocl * 20 + kq * 4, src + (size_t)(Rw + ocl) * Ksrc + kc + kq * 8);
    }
    CP_COMMIT();
}

// 2 m-tiles (32 oc) x 16 n-tiles (128 cols), 2 k16-steps per 32-k chunk
__device__ __forceinline__ void gemm_chunk(const unsigned* wt, const unsigned* sB,
                                           int lane, float acc[2][16][4]) {
    int grp = lane >> 2, tig = lane & 3;
    #pragma unroll
    for (int ks = 0; ks < 2; ks++) {
        int kp8 = ks * 8;
        unsigned a[2][4];
        #pragma unroll
        for (int m = 0; m < 2; m++) {
            const unsigned* r0 = wt + (m * 16 + grp) * 20 + kp8;
            const unsigned* r8 = wt + (m * 16 + grp + 8) * 20 + kp8;
            a[m][0] = r0[tig];
            a[m][1] = r8[tig];
            a[m][2] = r0[tig + 4];
            a[m][3] = r8[tig + 4];
        }
        const unsigned* x0r = sB + (kp8 + tig) * SXW;
        const unsigned* x4r = sB + (kp8 + tig + 4) * SXW;
        #pragma unroll
        for (int j = 0; j < 16; j++) {
            unsigned bf[2];
            int cb = j * 8 + grp;
            bf[0] = x0r[cb];
            bf[1] = x4r[cb];
            mma16(acc[0][j], a[0], bf);
            mma16(acc[1][j], a[1], bf);
        }
    }
}

// ------------------- K4: fused MLP (fp16, TN=128) + channel max -------------------
__global__ void __launch_bounds__(256, 1)
mlp_kernel(const float* __restrict__ points1, const float* __restrict__ pb1,
           float* __restrict__ out) {
    extern __shared__ unsigned sm32[];
    __half2* sX2  = (__half2*)sm32;           // [192 kp][SXW]; kp 0..127 reused as Y
    __half*  sYh  = (__half*)sm32;
    unsigned* sW  = sm32 + SX_U;              // 8 warps x 3 bufs x WTU
    int*     sOutI = (int*)(sm32 + SX_U + SW_U);

    int b  = blockIdx.y;
    int n0 = blockIdx.x * TN;
    int tid = threadIdx.x;
    int warp = tid >> 5, lane = tid & 31;
    int grp = lane >> 2, tig = lane & 3;
    int Rw = warp * 32;

    issue_w(0, warp, lane, sW);
    issue_w(1, warp, lane, sW);

    // ---- Phase A: build X as half2 words [kp][n], n = 0..127 ----
    for (int idx = tid; idx < 64 * TN; idx += 256) {
        int kp = idx >> 7, n = idx & 127;     // kp 0..63 (k 0..127), pb1 -> kp 128..191
        const float* p1r = points1 + ((size_t)b * CC + 2 * kp) * N1 + n0 + n;
        sX2[kp * SXW + n] = __floats2half2_rn(p1r[0], p1r[N1]);
        const float* pbr = pb1 + ((size_t)b * CC + 2 * kp) * N1 + n0 + n;
        sX2[(128 + kp) * SXW + n] = __floats2half2_rn(pbr[0], pbr[N1]);
    }
    // fused section: kp 64..127 (k 128..255), 16 queries per warp
    for (int qq = 0; qq < 16; qq++) {
        int q = warp * 16 + qq;
        int n = n0 + q;
        float4 wv = g_w4[b * N1 + n];
        int4   iv = g_i4[b * N1 + n];
        const float2* r0 = (const float2*)&g_p2t[((size_t)b * N2 + iv.x) * CC];
        const float2* r1 = (const float2*)&g_p2t[((size_t)b * N2 + iv.y) * CC];
        const float2* r2 = (const float2*)&g_p2t[((size_t)b * N2 + iv.z) * CC];
        #pragma unroll
        for (int i = 0; i < 2; i++) {
            int cp = lane + 32 * i;           // channel-pair 0..63
            float2 e0 = r0[cp], e1 = r1[cp], e2 = r2[cp];
            float vx = wv.x * e0.x + wv.y * e1.x + wv.z * e2.x;
            float vy = wv.x * e0.y + wv.y * e1.y + wv.z * e2.y;
            sX2[(64 + cp) * SXW + q] = __floats2half2_rn(vx, vy);
        }
    }
    __syncthreads();

    // ---- GEMM1: barrier-free per-warp W pipeline, 12 chunks ----
    float acc[2][16][4];
    #pragma unroll
    for (int m = 0; m < 2; m++)
        #pragma unroll
        for (int j = 0; j < 16; j++)
            #pragma unroll
            for (int e = 0; e < 4; e++) acc[m][j][e] = 0.f;

    for (int c = 0; c < 12; c++) {
        CPW1();
        issue_w(c + 2, warp, lane, sW);
        gemm_chunk(sW + warp * (3 * WTU) + (c % 3) * WTU, sm32 + c * 16 * SXW, lane, acc);
    }
    __syncthreads();   // all warps done reading X kp 0..127 before Y overwrites

    // ---- epilogue 1: bias + ReLU -> Y halves (warp's own 32 oc rows) ----
    {
        float bz[4];
        #pragma unroll
        for (int i = 0; i < 4; i++) bz[i] = g_b0f[Rw + grp + 8 * i];
        #pragma unroll
        for (int m = 0; m < 2; m++)
            #pragma unroll
            for (int j = 0; j < 16; j++) {
                int oc0 = Rw + 16 * m + grp;
                int oc1 = oc0 + 8;
                int col = 8 * j + 2 * tig;
                float v00 = fmaxf(acc[m][j][0] + bz[2 * m], 0.f);
                float v01 = fmaxf(acc[m][j][1] + bz[2 * m], 0.f);
                float v10 = fmaxf(acc[m][j][2] + bz[2 * m + 1], 0.f);
                float v11 = fmaxf(acc[m][j][3] + bz[2 * m + 1], 0.f);
                int h0 = (oc0 >> 1) * (2 * SXW) + (oc0 & 1);
                int h1 = (oc1 >> 1) * (2 * SXW) + (oc1 & 1);
                sYh[h0 + 2 * col]       = __float2half_rn(v00);
                sYh[h0 + 2 * (col + 1)] = __float2half_rn(v01);
                sYh[h1 + 2 * col]       = __float2half_rn(v10);
                sYh[h1 + 2 * (col + 1)] = __float2half_rn(v11);
            }
    }
    __syncthreads();   // Y visible to all before GEMM2 reads

    // ---- GEMM2: chunks 12..19 over Y (kp 0..127) ----
    float ac2[2][16][4];
    #pragma unroll
    for (int m = 0; m < 2; m++)
        #pragma unroll
        for (int j = 0; j < 16; j++)
            #pragma unroll
            for (int e = 0; e < 4; e++) ac2[m][j][e] = 0.f;

    for (int c = 12; c < 20; c++) {
        if (c == 19) { CPW0(); } else { CPW1(); }
        if (c + 2 < 20) issue_w(c + 2, warp, lane, sW);
        gemm_chunk(sW + warp * (3 * WTU) + (c % 3) * WTU,
                   sm32 + (c - 12) * 16 * SXW, lane, ac2);
    }

    // ---- epilogue 2: bias + ReLU + channel max ----
    float bz1[4];
    #pragma unroll
    for (int i = 0; i < 4; i++) bz1[i] = g_b1f[Rw + grp + 8 * i];

    if (tid < TN) sOutI[tid] = 0;   // ReLU output >= 0 -> int 0 valid identity
    __syncthreads();

    #pragma unroll
    for (int j = 0; j < 16; j++) {
        #pragma unroll
        for (int e = 0; e < 2; e++) {
            int col = 8 * j + 2 * tig + e;
            float v =    fmaxf(ac2[0][j][e]     + bz1[0], 0.f);
            v = fmaxf(v, fmaxf(ac2[0][j][e + 2] + bz1[1], 0.f));
            v = fmaxf(v, fmaxf(ac2[1][j][e]     + bz1[2], 0.f));
            v = fmaxf(v, fmaxf(ac2[1][j][e + 2] + bz1[3], 0.f));
            v = fmaxf(v, __shfl_xor_sync(0xffffffffu, v, 4));
            v = fmaxf(v, __shfl_xor_sync(0xffffffffu, v, 8));
            v = fmaxf(v, __shfl_xor_sync(0xffffffffu, v, 16));
            if (grp == 0) atomicMax(&sOutI[col], __float_as_int(v));
        }
    }
    __syncthreads();
    if (tid < TN) out[(size_t)b * N1 + n0 + tid] = __int_as_float(sOutI[tid]);
}

// ------------------- launch -------------------
extern "C" void kernel_launch(void* const* d_in, const int* in_sizes, int n_in,
                              void* d_out, int out_size) {
    const float* xyz1    = (const float*)d_in[0];
    const float* xyz2    = (const float*)d_in[1];
    const float* points2 = (const float*)d_in[2];
    const float* points1 = (const float*)d_in[3];
    const float* pb1     = (const float*)d_in[4];
    const float* w0  = (const float*)d_in[5];
    const float* b0  = (const float*)d_in[6];
    const float* g0  = (const float*)d_in[7];
    const float* be0 = (const float*)d_in[8];
    const float* m0  = (const float*)d_in[9];
    const float* v0  = (const float*)d_in[10];
    const float* w1  = (const float*)d_in[11];
    const float* b1  = (const float*)d_in[12];
    const float* g1  = (const float*)d_in[13];
    const float* be1 = (const float*)d_in[14];
    const float* m1  = (const float*)d_in[15];
    const float* v1  = (const float*)d_in[16];
    float* out = (float*)d_out;

    cudaFuncSetAttribute(mlp_kernel, cudaFuncAttributeMaxDynamicSharedMemorySize,
                         SMEM_MLP_BYTES);

    prep_kernel<<<PREP_END, 256>>>(points2, xyz2,
                                   w0, b0, g0, be0, m0, v0,
                                   w1, b1, g1, be1, m1, v1);
    knn_part<<<dim3(N1 / 512, SEG, BB), 256>>>(xyz1);
    knn_merge<<<(BB * N1 + 255) / 256, 256>>>(xyz1);
    mlp_kernel<<<dim3(N1 / TN, BB), 256, SMEM_MLP_BYTES>>>(points1, pb1, out);
}